// round 12
// baseline (speedup 1.0000x reference)
#include <cuda_runtime.h>
#include <cuda_fp16.h>
#include <math.h>
#include <cstdint>

#define C_ 256
#define G_ 16
#define CPG 16
#define N_ 8
#define H_ 80
#define W_ 80
#define HW 6400
#define CHW (C_*HW)
#define NCHW (N_*C_*HW)
#define EPSV 1e-5f
#define NBLK 50
#define NGTOT (N_*G_)

// fp16 tensor planes
__device__ __half g_xh[NCHW];
__device__ __half g_h0[NCHW];
__device__ __half g_hh[NCHW];
__device__ __half g_fu[NCHW];
__device__ __half g_gt[NCHW];
__device__ __half g_dh[NCHW];
__device__ __half g_y[NCHW];
__device__ __half g_wh[3*C_*C_];
__device__ float g_partials1[2 * NGTOT * NBLK];
__device__ float g_partials2[2 * NGTOT * NBLK];

__device__ __forceinline__ uint32_t smem_u32(const void* p) {
    uint32_t a;
    asm("{ .reg .u64 t; cvta.to.shared.u64 t, %1; cvt.u32.u64 %0, t; }"
        : "=r"(a) : "l"(p));
    return a;
}
#define CP_ASYNC16(dst, src) \
    asm volatile("cp.async.cg.shared.global [%0], [%1], 16;" :: "r"(dst), "l"(src))
#define CP_COMMIT() asm volatile("cp.async.commit_group;" ::: "memory")
#define CP_WAIT(n)  asm volatile("cp.async.wait_group %0;" :: "n"(n) : "memory")

// smem: A resident [128 x 264 halfs] = 67584 B, B ring 4 x [32 x 136 halfs]
#define A_STRIDE 264
#define A_BYTES  (128*A_STRIDE*2)
#define B_STRIDE 136
#define B_STAGE  (32*B_STRIDE*2)
#define NSTAGE   4
#define GEMM_SMEM (A_BYTES + NSTAGE*B_STAGE)

__device__ __forceinline__ void ldsm_x4(uint32_t* r, uint32_t addr) {
    asm volatile("ldmatrix.sync.aligned.m8n8.x4.shared.b16 {%0,%1,%2,%3}, [%4];"
        : "=r"(r[0]), "=r"(r[1]), "=r"(r[2]), "=r"(r[3]) : "r"(addr));
}
__device__ __forceinline__ void ldsm_x2t(uint32_t* r, uint32_t addr) {
    asm volatile("ldmatrix.sync.aligned.m8n8.x2.trans.shared.b16 {%0,%1}, [%2];"
        : "=r"(r[0]), "=r"(r[1]) : "r"(addr));
}
__device__ __forceinline__ void mma_f16(float* c, const uint32_t* a, const uint32_t* b) {
    asm volatile(
        "mma.sync.aligned.m16n8k16.row.col.f32.f16.f16.f32 "
        "{%0,%1,%2,%3}, {%4,%5,%6,%7}, {%8,%9}, {%0,%1,%2,%3};"
        : "+f"(c[0]), "+f"(c[1]), "+f"(c[2]), "+f"(c[3])
        : "r"(a[0]), "r"(a[1]), "r"(a[2]), "r"(a[3]), "r"(b[0]), "r"(b[1]));
}
// sigmoid via tanh.approx.f32 (1 MUFU op)
__device__ __forceinline__ float sigm(float v) {
    float t;
    asm("tanh.approx.f32 %0, %1;" : "=f"(t) : "f"(v * 0.5f));
    return fmaf(0.5f, t, 0.5f);
}

__device__ __forceinline__ void issue_b(uint32_t sbase, int tid, int k0, int n0,
                                        const __half* Bx) {
#pragma unroll
    for (int j = 0; j < 2; j++) {
        int i = tid + 256 * j;
        int kk = i >> 4, seg = i & 15;
        uint32_t dst = sbase + (uint32_t)(kk * (B_STRIDE * 2) + seg * 16);
        CP_ASYNC16(dst, Bx + (size_t)(k0 + kk) * HW + n0 + seg * 8);
    }
}

template<int MODE>
__global__ __launch_bounds__(256, 2)
void gemm_mma(const __half* __restrict__ Wh, const __half* __restrict__ Bx,
              __half* __restrict__ Y,
              float* __restrict__ partials,
              const __half* __restrict__ fusedsrc,
              const float* __restrict__ b_gate) {
    extern __shared__ char smem[];
    __shared__ float sred[8][4][2];
    const uint32_t sb = smem_u32(smem);
    const uint32_t bb = sb + A_BYTES;
    const int tid = threadIdx.x;
    const int lane = tid & 31;
    const int w = tid >> 5;
    const int wm = w & 1;
    const int wn = w >> 1;
    const int n0 = blockIdx.x * 128;
    const int m0 = blockIdx.y * 128;
    const __half* Bn = Bx + (size_t)blockIdx.z * CHW;
    __half* Yn = Y + (size_t)blockIdx.z * CHW;

    float acc[4][4][4];
#pragma unroll
    for (int i = 0; i < 4; i++)
#pragma unroll
        for (int j = 0; j < 4; j++)
#pragma unroll
            for (int q = 0; q < 4; q++) acc[i][j][q] = 0.f;

#pragma unroll
    for (int j = 0; j < 16; j++) {
        int i = tid + 256 * j;
        int row = i >> 5, seg = i & 31;
        uint32_t dst = sb + (uint32_t)(row * (A_STRIDE * 2) + seg * 16);
        CP_ASYNC16(dst, Wh + (size_t)(m0 + row) * 256 + seg * 8);
    }
    issue_b(bb, tid, 0, n0, Bn);
    CP_COMMIT();
    issue_b(bb + B_STAGE, tid, 32, n0, Bn);
    CP_COMMIT();
    issue_b(bb + 2 * B_STAGE, tid, 64, n0, Bn);
    CP_COMMIT();

    const uint32_t a_lane_off = (uint32_t)((lane & 15) * A_STRIDE + ((lane >> 4) << 3)) * 2;
    const uint32_t b_lane_off = (uint32_t)((lane & 15) * B_STRIDE) * 2;

    for (int ch = 0; ch < 8; ch++) {
        const int st = ch & 3;
        if (ch < 6) { CP_WAIT(2); } else if (ch == 6) { CP_WAIT(1); } else { CP_WAIT(0); }
        __syncthreads();
        {
            const uint32_t a_chunk = sb + (uint32_t)(wm * 64) * (A_STRIDE * 2)
                                     + a_lane_off + (uint32_t)(ch * 32) * 2;
            const uint32_t SBB = bb + st * B_STAGE;
#pragma unroll
            for (int ks = 0; ks < 2; ks++) {
                const uint32_t kb = (uint32_t)(ks * 16);
                uint32_t ah[4][4], bh[4][2];
#pragma unroll
                for (int mt = 0; mt < 4; mt++) {
                    ldsm_x4(ah[mt], a_chunk + (uint32_t)(mt * 16) * (A_STRIDE * 2) + kb * 2);
                }
#pragma unroll
                for (int nt = 0; nt < 4; nt++) {
                    ldsm_x2t(bh[nt], SBB + b_lane_off + kb * (B_STRIDE * 2)
                                     + (uint32_t)(wn * 32 + nt * 8) * 2);
                }
#pragma unroll
                for (int mt = 0; mt < 4; mt++)
#pragma unroll
                    for (int nt = 0; nt < 4; nt++)
                        mma_f16(acc[mt][nt], ah[mt], bh[nt]);
            }
        }
        if (ch < 5) {
            issue_b(bb + ((ch + 3) & 3) * B_STAGE, tid, (ch + 3) * 32, n0, Bn);
            CP_COMMIT();
        }
    }

    if (MODE == 0) {
        float s[4], s2[4];
#pragma unroll
        for (int mt = 0; mt < 4; mt++) { s[mt] = 0.f; s2[mt] = 0.f; }
#pragma unroll
        for (int mt = 0; mt < 4; mt++) {
            const int r = m0 + wm * 64 + mt * 16 + (lane >> 2);
#pragma unroll
            for (int nt = 0; nt < 4; nt++) {
                const int cc = n0 + wn * 32 + nt * 8 + (lane & 3) * 2;
                __half2 p01 = __floats2half2_rn(acc[mt][nt][0], acc[mt][nt][1]);
                __half2 p23 = __floats2half2_rn(acc[mt][nt][2], acc[mt][nt][3]);
                *(__half2*)(Yn + (size_t)r * HW + cc) = p01;
                *(__half2*)(Yn + (size_t)(r + 8) * HW + cc) = p23;
#pragma unroll
                for (int q = 0; q < 4; q++) {
                    float v = acc[mt][nt][q];
                    s[mt] += v; s2[mt] += v * v;
                }
            }
        }
#pragma unroll
        for (int mt = 0; mt < 4; mt++) {
#pragma unroll
            for (int off = 16; off > 0; off >>= 1) {
                s[mt]  += __shfl_down_sync(0xFFFFFFFFu, s[mt], off);
                s2[mt] += __shfl_down_sync(0xFFFFFFFFu, s2[mt], off);
            }
        }
        __syncthreads();
        if (lane == 0) {
#pragma unroll
            for (int mt = 0; mt < 4; mt++) {
                sred[w][mt][0] = s[mt];
                sred[w][mt][1] = s2[mt];
            }
        }
        __syncthreads();
        if (tid < 8) {
            const int twm = tid >> 2, tmt = tid & 3;
            float S = 0.f, S2 = 0.f;
#pragma unroll
            for (int j = 0; j < 4; j++) {
                S  += sred[twm + 2 * j][tmt][0];
                S2 += sred[twm + 2 * j][tmt][1];
            }
            const int g = blockIdx.y * 8 + twm * 4 + tmt;
            const int ng = blockIdx.z * G_ + g;
            partials[ng * NBLK + blockIdx.x] = S;
            partials[NGTOT * NBLK + ng * NBLK + blockIdx.x] = S2;
        }
    } else {
        const __half* fn = fusedsrc + (size_t)blockIdx.z * CHW;
#pragma unroll
        for (int mt = 0; mt < 4; mt++) {
            const int r0 = m0 + wm * 64 + mt * 16 + (lane >> 2);
#pragma unroll
            for (int nt = 0; nt < 4; nt++) {
                const int cc = n0 + wn * 32 + nt * 8 + (lane & 3) * 2;
#pragma unroll
                for (int half = 0; half < 2; half++) {
                    const int r = r0 + half * 8;
                    const float bg = b_gate[r];
                    float2 fv = __half22float2(*(const __half2*)(fn + (size_t)r * HW + cc));
                    float o0 = fv.x * sigm(acc[mt][nt][half * 2 + 0] + bg);
                    float o1 = fv.y * sigm(acc[mt][nt][half * 2 + 1] + bg);
                    *(__half2*)(Yn + (size_t)r * HW + cc) = __floats2half2_rn(o0, o1);
                }
            }
        }
    }
}

// ---------------------------------------------------------------------------
// fp32 -> fp16, 8 floats per thread (16B store)
// ---------------------------------------------------------------------------
__global__ void cvt_x_k(const float* __restrict__ in, __half* __restrict__ o, int n8) {
    int i = blockIdx.x * 256 + threadIdx.x;
    if (i >= n8) return;
    float4 v0 = *(const float4*)(in + i * 8);
    float4 v1 = *(const float4*)(in + i * 8 + 4);
    __half2 a = __floats2half2_rn(v0.x, v0.y);
    __half2 b = __floats2half2_rn(v0.z, v0.w);
    __half2 c = __floats2half2_rn(v1.x, v1.y);
    __half2 d = __floats2half2_rn(v1.z, v1.w);
    uint4 pk = make_uint4(*(uint32_t*)&a, *(uint32_t*)&b, *(uint32_t*)&c, *(uint32_t*)&d);
    *(uint4*)(o + i * 8) = pk;
}
__global__ void cvt_w3_k(const float* __restrict__ w0, const float* __restrict__ w1,
                         const float* __restrict__ w2, __half* __restrict__ o) {
    const float* src = (blockIdx.y == 0) ? w0 : (blockIdx.y == 1) ? w1 : w2;
    __half* dst = o + (size_t)blockIdx.y * C_ * C_;
    int i = blockIdx.x * 256 + threadIdx.x;
    float4 v0 = *(const float4*)(src + i * 8);
    float4 v1 = *(const float4*)(src + i * 8 + 4);
    __half2 a = __floats2half2_rn(v0.x, v0.y);
    __half2 b = __floats2half2_rn(v0.z, v0.w);
    __half2 c = __floats2half2_rn(v1.x, v1.y);
    __half2 d = __floats2half2_rn(v1.z, v1.w);
    uint4 pk = make_uint4(*(uint32_t*)&a, *(uint32_t*)&b, *(uint32_t*)&c, *(uint32_t*)&d);
    *(uint4*)(dst + i * 8) = pk;
}

// ---------------------------------------------------------------------------
// in-block GN stats from partials (warp-parallel reduce of 50)
// ---------------------------------------------------------------------------
__device__ __forceinline__ void block_stats(const float* __restrict__ partials,
                                            int ng, int tid, float* smr,
                                            float& mean, float& rstd) {
    if (tid < 32) {
        float s = 0.f, s2 = 0.f;
        for (int i = tid; i < NBLK; i += 32) {
            s  += partials[ng * NBLK + i];
            s2 += partials[NGTOT * NBLK + ng * NBLK + i];
        }
#pragma unroll
        for (int off = 16; off > 0; off >>= 1) {
            s  += __shfl_down_sync(0xFFFFFFFFu, s, off);
            s2 += __shfl_down_sync(0xFFFFFFFFu, s2, off);
        }
        if (tid == 0) {
            const float M = (float)(CPG * HW);
            float mu = s / M;
            float var = s2 / M - mu * mu;
            smr[0] = mu;
            smr[1] = rsqrtf(var + EPSV);
        }
    }
    __syncthreads();
    mean = smr[0];
    rstd = smr[1];
}

// ---------------------------------------------------------------------------
// GN + SiLU + fused (stats in-block). 512 threads.
// ---------------------------------------------------------------------------
__global__ __launch_bounds__(512)
void gn_silu_rowcol_k(const __half* __restrict__ H0,
                      const float* __restrict__ partials,
                      const float* __restrict__ gamma,
                      const float* __restrict__ beta,
                      __half* __restrict__ Hh,
                      __half* __restrict__ F) {
    __shared__ float plane[HW];
    __shared__ float rs[H_], cs[W_];
    __shared__ float smr[2];
    const int nc = blockIdx.x;
    const int c = nc & (C_ - 1);
    const int ng = (nc >> 8) * G_ + (c >> 4);
    const int tid = threadIdx.x;
    float mean, rstd;
    block_stats(partials, ng, tid, smr, mean, rstd);
    const float ga = gamma[c];
    const float be = beta[c];
    const __half2* base = (const __half2*)(H0 + (size_t)nc * HW);
    __half2* hh = (__half2*)(Hh + (size_t)nc * HW);
    __half2* fb = (__half2*)(F + (size_t)nc * HW);

    for (int i = tid; i < HW / 2; i += 512) {
        float2 v = __half22float2(base[i]);
        v.x = (v.x - mean) * rstd * ga + be;
        v.y = (v.y - mean) * rstd * ga + be;
        v.x = v.x * sigm(v.x);
        v.y = v.y * sigm(v.y);
        plane[2 * i] = v.x;
        plane[2 * i + 1] = v.y;
        hh[i] = __floats2half2_rn(v.x, v.y);
    }
    __syncthreads();
    // 2 threads per row / per column (40 elems each + shfl combine)
    if (tid < 160) {
        const int y = tid >> 1, h = tid & 1;
        float s = 0.f;
#pragma unroll 8
        for (int x = h * 40; x < h * 40 + 40; x++) s += plane[y * W_ + x];
        s += __shfl_down_sync(0xFFFFFFFFu, s, 1);
        if (!h) rs[y] = s;
    } else if (tid < 320) {
        const int t = tid - 160;
        const int x = t >> 1, h = t & 1;
        float s = 0.f;
#pragma unroll 8
        for (int y = h * 40; y < h * 40 + 40; y++) s += plane[y * W_ + x];
        s += __shfl_down_sync(0xFFFFFFFFu, s, 1);
        if (!h) cs[x] = s;
    }
    __syncthreads();
    for (int i = tid; i < HW / 2; i += 512) {
        const int p0 = 2 * i;
        const int y = p0 / W_;
        const int x = p0 - y * W_;
        float f0 = 0.25f * (rs[y] + cs[x] + 2.f * plane[p0]);
        float f1 = 0.25f * (rs[y] + cs[x + 1] + 2.f * plane[p0 + 1]);
        fb[i] = __floats2half2_rn(f0, f1);
    }
}

// ---------------------------------------------------------------------------
// depthwise 3x3 — fp16 in/out; plane fp32 in smem. 512 threads.
// ---------------------------------------------------------------------------
__global__ __launch_bounds__(512)
void dw3x3_k(const __half* __restrict__ in,
             const float* __restrict__ wdw,
             __half* __restrict__ Oh) {
    __shared__ float pl[HW];
    const int nc = blockIdx.x;
    const int c = nc & (C_ - 1);
    float wr[9];
#pragma unroll
    for (int q = 0; q < 9; q++) wr[q] = __ldg(wdw + c * 9 + q);
    const __half2* p = (const __half2*)(in + (size_t)nc * HW);
    __half2* oh = (__half2*)(Oh + (size_t)nc * HW);
    for (int i = threadIdx.x; i < HW / 2; i += 512) {
        float2 v = __half22float2(p[i]);
        pl[2 * i] = v.x;
        pl[2 * i + 1] = v.y;
    }
    __syncthreads();
    for (int i = threadIdx.x; i < HW / 2; i += 512) {
        const int p0 = 2 * i;
        const int y = p0 / W_;
        const int x0 = p0 - y * W_;
        float o[2];
#pragma unroll
        for (int e = 0; e < 2; e++) {
            const int x = x0 + e;
            float s = 0.f;
#pragma unroll
            for (int dy = -1; dy <= 1; dy++) {
                const int yy = y + dy;
                if ((unsigned)yy >= H_) continue;
#pragma unroll
                for (int dx = -1; dx <= 1; dx++) {
                    const int xx = x + dx;
                    if ((unsigned)xx >= W_) continue;
                    s += wr[(dy + 1) * 3 + (dx + 1)] * pl[yy * W_ + xx];
                }
            }
            o[e] = s;
        }
        oh[i] = __floats2half2_rn(o[0], o[1]);
    }
}

// ---------------------------------------------------------------------------
// final: out = silu(gn(y)) per-plane, stats in-block. 512 threads.
// ---------------------------------------------------------------------------
__global__ __launch_bounds__(512)
void gn_silu_out_k(const __half* __restrict__ Yin,
                   const float* __restrict__ partials,
                   const float* __restrict__ gamma,
                   const float* __restrict__ beta,
                   float* __restrict__ out) {
    __shared__ float smr[2];
    const int nc = blockIdx.x;
    const int c = nc & (C_ - 1);
    const int ng = (nc >> 8) * G_ + (c >> 4);
    const int tid = threadIdx.x;
    float mean, rstd;
    block_stats(partials, ng, tid, smr, mean, rstd);
    const float ga = gamma[c];
    const float be = beta[c];
    const __half2* yp = (const __half2*)(Yin + (size_t)nc * HW);
    float* op = out + (size_t)nc * HW;
    for (int i = tid; i < HW / 2; i += 512) {
        float2 v = __half22float2(yp[i]);
        v.x = (v.x - mean) * rstd * ga + be;
        v.y = (v.y - mean) * rstd * ga + be;
        *(float2*)(op + 2 * i) = make_float2(v.x * sigm(v.x), v.y * sigm(v.y));
    }
}

// ---------------------------------------------------------------------------
extern "C" void kernel_launch(void* const* d_in, const int* in_sizes, int n_in,
                              void* d_out, int out_size) {
    const float* x      = (const float*)d_in[0];
    const float* w_pre  = (const float*)d_in[1];
    const float* g1     = (const float*)d_in[2];
    const float* b1     = (const float*)d_in[3];
    const float* w_gate = (const float*)d_in[4];
    const float* b_gate = (const float*)d_in[5];
    const float* w_dw   = (const float*)d_in[6];
    const float* w_pw   = (const float*)d_in[7];
    const float* g2     = (const float*)d_in[8];
    const float* b2     = (const float*)d_in[9];
    float* out = (float*)d_out;

    float *part1, *part2;
    __half *xh, *h0, *hh, *fu, *gt, *dh, *y16, *wh;
    cudaGetSymbolAddress((void**)&part1, g_partials1);
    cudaGetSymbolAddress((void**)&part2, g_partials2);
    cudaGetSymbolAddress((void**)&xh, g_xh);
    cudaGetSymbolAddress((void**)&h0, g_h0);
    cudaGetSymbolAddress((void**)&hh, g_hh);
    cudaGetSymbolAddress((void**)&fu, g_fu);
    cudaGetSymbolAddress((void**)&gt, g_gt);
    cudaGetSymbolAddress((void**)&dh, g_dh);
    cudaGetSymbolAddress((void**)&y16, g_y);
    cudaGetSymbolAddress((void**)&wh, g_wh);

    cudaFuncSetAttribute(gemm_mma<0>, cudaFuncAttributeMaxDynamicSharedMemorySize, GEMM_SMEM);
    cudaFuncSetAttribute(gemm_mma<1>, cudaFuncAttributeMaxDynamicSharedMemorySize, GEMM_SMEM);

    dim3 ggrid(NBLK, 2, N_);

    // 0) operand conversion
    cvt_w3_k<<<dim3(C_*C_/8/256, 3), 256>>>(w_pre, w_gate, w_pw, wh);
    cvt_x_k<<<NCHW/8/256, 256>>>(x, xh, NCHW/8);

    // 1) h0 = conv1x1(x, w_pre) [fp16] + GN1 partials
    gemm_mma<0><<<ggrid, 256, GEMM_SMEM>>>(wh, xh, h0, part1, nullptr, nullptr);
    // 2) h = silu(gn(h0)) -> fp16 + fused -> fp16
    gn_silu_rowcol_k<<<N_ * C_, 512>>>(h0, part1, g1, b1, hh, fu);
    // 3) gated = fused * sigmoid(conv1x1(h,w_gate)+b) -> fp16
    gemm_mma<1><<<ggrid, 256, GEMM_SMEM>>>(wh + C_*C_, hh, gt, nullptr, fu, b_gate);
    // 4) depthwise 3x3 fp16 -> fp16
    dw3x3_k<<<N_ * C_, 512>>>(gt, w_dw, dh);
    // 5) y = conv1x1(dw, w_pw) [fp16] + GN2 partials
    gemm_mma<0><<<ggrid, 256, GEMM_SMEM>>>(wh + 2*C_*C_, dh, y16, part2, nullptr, nullptr);
    // 6) out = silu(gn(y)) -> fp32
    gn_silu_out_k<<<N_ * C_, 512>>>(y16, part2, g2, b2, out);
}

// round 13
// speedup vs baseline: 1.0010x; 1.0010x over previous
#include <cuda_runtime.h>
#include <cuda_fp16.h>
#include <math.h>
#include <cstdint>

#define C_ 256
#define G_ 16
#define CPG 16
#define N_ 8
#define H_ 80
#define W_ 80
#define HW 6400
#define CHW (C_*HW)
#define NCHW (N_*C_*HW)
#define EPSV 1e-5f
#define NBLK 50
#define NGTOT (N_*G_)

// fp16 tensor planes
__device__ __half g_xh[NCHW];
__device__ __half g_h0[NCHW];
__device__ __half g_hh[NCHW];
__device__ __half g_fu[NCHW];
__device__ __half g_gt[NCHW];
__device__ __half g_dh[NCHW];
__device__ __half g_y[NCHW];
__device__ __half g_wh[3*C_*C_];
__device__ float g_partials1[2 * NGTOT * NBLK];
__device__ float g_partials2[2 * NGTOT * NBLK];

__device__ __forceinline__ uint32_t smem_u32(const void* p) {
    uint32_t a;
    asm("{ .reg .u64 t; cvta.to.shared.u64 t, %1; cvt.u32.u64 %0, t; }"
        : "=r"(a) : "l"(p));
    return a;
}
#define CP_ASYNC16(dst, src) \
    asm volatile("cp.async.cg.shared.global [%0], [%1], 16;" :: "r"(dst), "l"(src))
#define CP_COMMIT() asm volatile("cp.async.commit_group;" ::: "memory")
#define CP_WAIT(n)  asm volatile("cp.async.wait_group %0;" :: "n"(n) : "memory")

// smem: A resident [128 x 264 halfs] = 67584 B, B ring 4 x [32 x 136 halfs]
#define A_STRIDE 264
#define A_BYTES  (128*A_STRIDE*2)
#define B_STRIDE 136
#define B_STAGE  (32*B_STRIDE*2)
#define NSTAGE   4
#define GEMM_SMEM (A_BYTES + NSTAGE*B_STAGE)

__device__ __forceinline__ void ldsm_x4(uint32_t* r, uint32_t addr) {
    asm volatile("ldmatrix.sync.aligned.m8n8.x4.shared.b16 {%0,%1,%2,%3}, [%4];"
        : "=r"(r[0]), "=r"(r[1]), "=r"(r[2]), "=r"(r[3]) : "r"(addr));
}
__device__ __forceinline__ void ldsm_x2t(uint32_t* r, uint32_t addr) {
    asm volatile("ldmatrix.sync.aligned.m8n8.x2.trans.shared.b16 {%0,%1}, [%2];"
        : "=r"(r[0]), "=r"(r[1]) : "r"(addr));
}
__device__ __forceinline__ void mma_f16(float* c, const uint32_t* a, const uint32_t* b) {
    asm volatile(
        "mma.sync.aligned.m16n8k16.row.col.f32.f16.f16.f32 "
        "{%0,%1,%2,%3}, {%4,%5,%6,%7}, {%8,%9}, {%0,%1,%2,%3};"
        : "+f"(c[0]), "+f"(c[1]), "+f"(c[2]), "+f"(c[3])
        : "r"(a[0]), "r"(a[1]), "r"(a[2]), "r"(a[3]), "r"(b[0]), "r"(b[1]));
}
// sigmoid via tanh.approx.f32 (1 MUFU op)
__device__ __forceinline__ float sigm(float v) {
    float t;
    asm("tanh.approx.f32 %0, %1;" : "=f"(t) : "f"(v * 0.5f));
    return fmaf(0.5f, t, 0.5f);
}

__device__ __forceinline__ void issue_b(uint32_t sbase, int tid, int k0, int n0,
                                        const __half* Bx) {
#pragma unroll
    for (int j = 0; j < 2; j++) {
        int i = tid + 256 * j;
        int kk = i >> 4, seg = i & 15;
        uint32_t dst = sbase + (uint32_t)(kk * (B_STRIDE * 2) + seg * 16);
        CP_ASYNC16(dst, Bx + (size_t)(k0 + kk) * HW + n0 + seg * 8);
    }
}

template<int MODE>
__global__ __launch_bounds__(256, 2)
void gemm_mma(const __half* __restrict__ Wh, const __half* __restrict__ Bx,
              __half* __restrict__ Y,
              float* __restrict__ partials,
              const __half* __restrict__ fusedsrc,
              const float* __restrict__ b_gate) {
    extern __shared__ char smem[];
    __shared__ float sred[8][4][2];
    const uint32_t sb = smem_u32(smem);
    const uint32_t bb = sb + A_BYTES;
    const int tid = threadIdx.x;
    const int lane = tid & 31;
    const int w = tid >> 5;
    const int wm = w & 1;
    const int wn = w >> 1;
    const int n0 = blockIdx.x * 128;
    const int m0 = blockIdx.y * 128;
    const __half* Bn = Bx + (size_t)blockIdx.z * CHW;
    __half* Yn = Y + (size_t)blockIdx.z * CHW;

    float acc[4][4][4];
#pragma unroll
    for (int i = 0; i < 4; i++)
#pragma unroll
        for (int j = 0; j < 4; j++)
#pragma unroll
            for (int q = 0; q < 4; q++) acc[i][j][q] = 0.f;

#pragma unroll
    for (int j = 0; j < 16; j++) {
        int i = tid + 256 * j;
        int row = i >> 5, seg = i & 31;
        uint32_t dst = sb + (uint32_t)(row * (A_STRIDE * 2) + seg * 16);
        CP_ASYNC16(dst, Wh + (size_t)(m0 + row) * 256 + seg * 8);
    }
    issue_b(bb, tid, 0, n0, Bn);
    CP_COMMIT();
    issue_b(bb + B_STAGE, tid, 32, n0, Bn);
    CP_COMMIT();
    issue_b(bb + 2 * B_STAGE, tid, 64, n0, Bn);
    CP_COMMIT();

    const uint32_t a_lane_off = (uint32_t)((lane & 15) * A_STRIDE + ((lane >> 4) << 3)) * 2;
    const uint32_t b_lane_off = (uint32_t)((lane & 15) * B_STRIDE) * 2;

    for (int ch = 0; ch < 8; ch++) {
        const int st = ch & 3;
        if (ch < 6) { CP_WAIT(2); } else if (ch == 6) { CP_WAIT(1); } else { CP_WAIT(0); }
        __syncthreads();
        {
            const uint32_t a_chunk = sb + (uint32_t)(wm * 64) * (A_STRIDE * 2)
                                     + a_lane_off + (uint32_t)(ch * 32) * 2;
            const uint32_t SBB = bb + st * B_STAGE;
#pragma unroll
            for (int ks = 0; ks < 2; ks++) {
                const uint32_t kb = (uint32_t)(ks * 16);
                uint32_t ah[4][4], bh[4][2];
#pragma unroll
                for (int mt = 0; mt < 4; mt++) {
                    ldsm_x4(ah[mt], a_chunk + (uint32_t)(mt * 16) * (A_STRIDE * 2) + kb * 2);
                }
#pragma unroll
                for (int nt = 0; nt < 4; nt++) {
                    ldsm_x2t(bh[nt], SBB + b_lane_off + kb * (B_STRIDE * 2)
                                     + (uint32_t)(wn * 32 + nt * 8) * 2);
                }
#pragma unroll
                for (int mt = 0; mt < 4; mt++)
#pragma unroll
                    for (int nt = 0; nt < 4; nt++)
                        mma_f16(acc[mt][nt], ah[mt], bh[nt]);
            }
        }
        if (ch < 5) {
            issue_b(bb + ((ch + 3) & 3) * B_STAGE, tid, (ch + 3) * 32, n0, Bn);
            CP_COMMIT();
        }
    }

    if (MODE == 0) {
        float s[4], s2[4];
#pragma unroll
        for (int mt = 0; mt < 4; mt++) { s[mt] = 0.f; s2[mt] = 0.f; }
#pragma unroll
        for (int mt = 0; mt < 4; mt++) {
            const int r = m0 + wm * 64 + mt * 16 + (lane >> 2);
#pragma unroll
            for (int nt = 0; nt < 4; nt++) {
                const int cc = n0 + wn * 32 + nt * 8 + (lane & 3) * 2;
                __half2 p01 = __floats2half2_rn(acc[mt][nt][0], acc[mt][nt][1]);
                __half2 p23 = __floats2half2_rn(acc[mt][nt][2], acc[mt][nt][3]);
                *(__half2*)(Yn + (size_t)r * HW + cc) = p01;
                *(__half2*)(Yn + (size_t)(r + 8) * HW + cc) = p23;
#pragma unroll
                for (int q = 0; q < 4; q++) {
                    float v = acc[mt][nt][q];
                    s[mt] += v; s2[mt] += v * v;
                }
            }
        }
#pragma unroll
        for (int mt = 0; mt < 4; mt++) {
#pragma unroll
            for (int off = 16; off > 0; off >>= 1) {
                s[mt]  += __shfl_down_sync(0xFFFFFFFFu, s[mt], off);
                s2[mt] += __shfl_down_sync(0xFFFFFFFFu, s2[mt], off);
            }
        }
        __syncthreads();
        if (lane == 0) {
#pragma unroll
            for (int mt = 0; mt < 4; mt++) {
                sred[w][mt][0] = s[mt];
                sred[w][mt][1] = s2[mt];
            }
        }
        __syncthreads();
        if (tid < 8) {
            const int twm = tid >> 2, tmt = tid & 3;
            float S = 0.f, S2 = 0.f;
#pragma unroll
            for (int j = 0; j < 4; j++) {
                S  += sred[twm + 2 * j][tmt][0];
                S2 += sred[twm + 2 * j][tmt][1];
            }
            const int g = blockIdx.y * 8 + twm * 4 + tmt;
            const int ng = blockIdx.z * G_ + g;
            partials[ng * NBLK + blockIdx.x] = S;
            partials[NGTOT * NBLK + ng * NBLK + blockIdx.x] = S2;
        }
    } else {
        const __half* fn = fusedsrc + (size_t)blockIdx.z * CHW;
#pragma unroll
        for (int mt = 0; mt < 4; mt++) {
            const int r0 = m0 + wm * 64 + mt * 16 + (lane >> 2);
#pragma unroll
            for (int nt = 0; nt < 4; nt++) {
                const int cc = n0 + wn * 32 + nt * 8 + (lane & 3) * 2;
#pragma unroll
                for (int half = 0; half < 2; half++) {
                    const int r = r0 + half * 8;
                    const float bg = b_gate[r];
                    float2 fv = __half22float2(*(const __half2*)(fn + (size_t)r * HW + cc));
                    float o0 = fv.x * sigm(acc[mt][nt][half * 2 + 0] + bg);
                    float o1 = fv.y * sigm(acc[mt][nt][half * 2 + 1] + bg);
                    *(__half2*)(Yn + (size_t)r * HW + cc) = __floats2half2_rn(o0, o1);
                }
            }
        }
    }
}

// ---------------------------------------------------------------------------
// fp32 -> fp16, 8 floats per thread (16B store)
// ---------------------------------------------------------------------------
__global__ void cvt_x_k(const float* __restrict__ in, __half* __restrict__ o, int n8) {
    int i = blockIdx.x * 256 + threadIdx.x;
    if (i >= n8) return;
    float4 v0 = *(const float4*)(in + i * 8);
    float4 v1 = *(const float4*)(in + i * 8 + 4);
    __half2 a = __floats2half2_rn(v0.x, v0.y);
    __half2 b = __floats2half2_rn(v0.z, v0.w);
    __half2 c = __floats2half2_rn(v1.x, v1.y);
    __half2 d = __floats2half2_rn(v1.z, v1.w);
    uint4 pk = make_uint4(*(uint32_t*)&a, *(uint32_t*)&b, *(uint32_t*)&c, *(uint32_t*)&d);
    *(uint4*)(o + i * 8) = pk;
}
__global__ void cvt_w3_k(const float* __restrict__ w0, const float* __restrict__ w1,
                         const float* __restrict__ w2, __half* __restrict__ o) {
    const float* src = (blockIdx.y == 0) ? w0 : (blockIdx.y == 1) ? w1 : w2;
    __half* dst = o + (size_t)blockIdx.y * C_ * C_;
    int i = blockIdx.x * 256 + threadIdx.x;
    float4 v0 = *(const float4*)(src + i * 8);
    float4 v1 = *(const float4*)(src + i * 8 + 4);
    __half2 a = __floats2half2_rn(v0.x, v0.y);
    __half2 b = __floats2half2_rn(v0.z, v0.w);
    __half2 c = __floats2half2_rn(v1.x, v1.y);
    __half2 d = __floats2half2_rn(v1.z, v1.w);
    uint4 pk = make_uint4(*(uint32_t*)&a, *(uint32_t*)&b, *(uint32_t*)&c, *(uint32_t*)&d);
    *(uint4*)(dst + i * 8) = pk;
}

// ---------------------------------------------------------------------------
// in-block GN stats from partials (warp-parallel reduce of 50)
// ---------------------------------------------------------------------------
__device__ __forceinline__ void block_stats(const float* __restrict__ partials,
                                            int ng, int tid, float* smr,
                                            float& mean, float& rstd) {
    if (tid < 32) {
        float s = 0.f, s2 = 0.f;
        for (int i = tid; i < NBLK; i += 32) {
            s  += partials[ng * NBLK + i];
            s2 += partials[NGTOT * NBLK + ng * NBLK + i];
        }
#pragma unroll
        for (int off = 16; off > 0; off >>= 1) {
            s  += __shfl_down_sync(0xFFFFFFFFu, s, off);
            s2 += __shfl_down_sync(0xFFFFFFFFu, s2, off);
        }
        if (tid == 0) {
            const float M = (float)(CPG * HW);
            float mu = s / M;
            float var = s2 / M - mu * mu;
            smr[0] = mu;
            smr[1] = rsqrtf(var + EPSV);
        }
    }
    __syncthreads();
    mean = smr[0];
    rstd = smr[1];
}

// ---------------------------------------------------------------------------
// GN + SiLU + fused (stats in-block). 512 threads.
// ---------------------------------------------------------------------------
__global__ __launch_bounds__(512)
void gn_silu_rowcol_k(const __half* __restrict__ H0,
                      const float* __restrict__ partials,
                      const float* __restrict__ gamma,
                      const float* __restrict__ beta,
                      __half* __restrict__ Hh,
                      __half* __restrict__ F) {
    __shared__ float plane[HW];
    __shared__ float rs[H_], cs[W_];
    __shared__ float smr[2];
    const int nc = blockIdx.x;
    const int c = nc & (C_ - 1);
    const int ng = (nc >> 8) * G_ + (c >> 4);
    const int tid = threadIdx.x;
    float mean, rstd;
    block_stats(partials, ng, tid, smr, mean, rstd);
    const float ga = gamma[c];
    const float be = beta[c];
    const __half2* base = (const __half2*)(H0 + (size_t)nc * HW);
    __half2* hh = (__half2*)(Hh + (size_t)nc * HW);
    __half2* fb = (__half2*)(F + (size_t)nc * HW);

    for (int i = tid; i < HW / 2; i += 512) {
        float2 v = __half22float2(base[i]);
        v.x = (v.x - mean) * rstd * ga + be;
        v.y = (v.y - mean) * rstd * ga + be;
        v.x = v.x * sigm(v.x);
        v.y = v.y * sigm(v.y);
        plane[2 * i] = v.x;
        plane[2 * i + 1] = v.y;
        hh[i] = __floats2half2_rn(v.x, v.y);
    }
    __syncthreads();
    // 2 threads per row / per column (40 elems each + shfl combine)
    if (tid < 160) {
        const int y = tid >> 1, h = tid & 1;
        float s = 0.f;
#pragma unroll 8
        for (int x = h * 40; x < h * 40 + 40; x++) s += plane[y * W_ + x];
        s += __shfl_down_sync(0xFFFFFFFFu, s, 1);
        if (!h) rs[y] = s;
    } else if (tid < 320) {
        const int t = tid - 160;
        const int x = t >> 1, h = t & 1;
        float s = 0.f;
#pragma unroll 8
        for (int y = h * 40; y < h * 40 + 40; y++) s += plane[y * W_ + x];
        s += __shfl_down_sync(0xFFFFFFFFu, s, 1);
        if (!h) cs[x] = s;
    }
    __syncthreads();
    for (int i = tid; i < HW / 2; i += 512) {
        const int p0 = 2 * i;
        const int y = p0 / W_;
        const int x = p0 - y * W_;
        float f0 = 0.25f * (rs[y] + cs[x] + 2.f * plane[p0]);
        float f1 = 0.25f * (rs[y] + cs[x + 1] + 2.f * plane[p0 + 1]);
        fb[i] = __floats2half2_rn(f0, f1);
    }
}

// ---------------------------------------------------------------------------
// depthwise 3x3 — fp16 in/out; plane fp32 in smem. 512 threads.
// ---------------------------------------------------------------------------
__global__ __launch_bounds__(512)
void dw3x3_k(const __half* __restrict__ in,
             const float* __restrict__ wdw,
             __half* __restrict__ Oh) {
    __shared__ float pl[HW];
    const int nc = blockIdx.x;
    const int c = nc & (C_ - 1);
    float wr[9];
#pragma unroll
    for (int q = 0; q < 9; q++) wr[q] = __ldg(wdw + c * 9 + q);
    const __half2* p = (const __half2*)(in + (size_t)nc * HW);
    __half2* oh = (__half2*)(Oh + (size_t)nc * HW);
    for (int i = threadIdx.x; i < HW / 2; i += 512) {
        float2 v = __half22float2(p[i]);
        pl[2 * i] = v.x;
        pl[2 * i + 1] = v.y;
    }
    __syncthreads();
    for (int i = threadIdx.x; i < HW / 2; i += 512) {
        const int p0 = 2 * i;
        const int y = p0 / W_;
        const int x0 = p0 - y * W_;
        float o[2];
#pragma unroll
        for (int e = 0; e < 2; e++) {
            const int x = x0 + e;
            float s = 0.f;
#pragma unroll
            for (int dy = -1; dy <= 1; dy++) {
                const int yy = y + dy;
                if ((unsigned)yy >= H_) continue;
#pragma unroll
                for (int dx = -1; dx <= 1; dx++) {
                    const int xx = x + dx;
                    if ((unsigned)xx >= W_) continue;
                    s += wr[(dy + 1) * 3 + (dx + 1)] * pl[yy * W_ + xx];
                }
            }
            o[e] = s;
        }
        oh[i] = __floats2half2_rn(o[0], o[1]);
    }
}

// ---------------------------------------------------------------------------
// final: out = silu(gn(y)) per-plane, stats in-block. 512 threads.
// ---------------------------------------------------------------------------
__global__ __launch_bounds__(512)
void gn_silu_out_k(const __half* __restrict__ Yin,
                   const float* __restrict__ partials,
                   const float* __restrict__ gamma,
                   const float* __restrict__ beta,
                   float* __restrict__ out) {
    __shared__ float smr[2];
    const int nc = blockIdx.x;
    const int c = nc & (C_ - 1);
    const int ng = (nc >> 8) * G_ + (c >> 4);
    const int tid = threadIdx.x;
    float mean, rstd;
    block_stats(partials, ng, tid, smr, mean, rstd);
    const float ga = gamma[c];
    const float be = beta[c];
    const __half2* yp = (const __half2*)(Yin + (size_t)nc * HW);
    float* op = out + (size_t)nc * HW;
    for (int i = tid; i < HW / 2; i += 512) {
        float2 v = __half22float2(yp[i]);
        v.x = (v.x - mean) * rstd * ga + be;
        v.y = (v.y - mean) * rstd * ga + be;
        *(float2*)(op + 2 * i) = make_float2(v.x * sigm(v.x), v.y * sigm(v.y));
    }
}

// ---------------------------------------------------------------------------
extern "C" void kernel_launch(void* const* d_in, const int* in_sizes, int n_in,
                              void* d_out, int out_size) {
    const float* x      = (const float*)d_in[0];
    const float* w_pre  = (const float*)d_in[1];
    const float* g1     = (const float*)d_in[2];
    const float* b1     = (const float*)d_in[3];
    const float* w_gate = (const float*)d_in[4];
    const float* b_gate = (const float*)d_in[5];
    const float* w_dw   = (const float*)d_in[6];
    const float* w_pw   = (const float*)d_in[7];
    const float* g2     = (const float*)d_in[8];
    const float* b2     = (const float*)d_in[9];
    float* out = (float*)d_out;

    float *part1, *part2;
    __half *xh, *h0, *hh, *fu, *gt, *dh, *y16, *wh;
    cudaGetSymbolAddress((void**)&part1, g_partials1);
    cudaGetSymbolAddress((void**)&part2, g_partials2);
    cudaGetSymbolAddress((void**)&xh, g_xh);
    cudaGetSymbolAddress((void**)&h0, g_h0);
    cudaGetSymbolAddress((void**)&hh, g_hh);
    cudaGetSymbolAddress((void**)&fu, g_fu);
    cudaGetSymbolAddress((void**)&gt, g_gt);
    cudaGetSymbolAddress((void**)&dh, g_dh);
    cudaGetSymbolAddress((void**)&y16, g_y);
    cudaGetSymbolAddress((void**)&wh, g_wh);

    cudaFuncSetAttribute(gemm_mma<0>, cudaFuncAttributeMaxDynamicSharedMemorySize, GEMM_SMEM);
    cudaFuncSetAttribute(gemm_mma<1>, cudaFuncAttributeMaxDynamicSharedMemorySize, GEMM_SMEM);

    dim3 ggrid(NBLK, 2, N_);

    // 0) operand conversion
    cvt_w3_k<<<dim3(C_*C_/8/256, 3), 256>>>(w_pre, w_gate, w_pw, wh);
    cvt_x_k<<<NCHW/8/256, 256>>>(x, xh, NCHW/8);

    // 1) h0 = conv1x1(x, w_pre) [fp16] + GN1 partials
    gemm_mma<0><<<ggrid, 256, GEMM_SMEM>>>(wh, xh, h0, part1, nullptr, nullptr);
    // 2) h = silu(gn(h0)) -> fp16 + fused -> fp16
    gn_silu_rowcol_k<<<N_ * C_, 512>>>(h0, part1, g1, b1, hh, fu);
    // 3) gated = fused * sigmoid(conv1x1(h,w_gate)+b) -> fp16
    gemm_mma<1><<<ggrid, 256, GEMM_SMEM>>>(wh + C_*C_, hh, gt, nullptr, fu, b_gate);
    // 4) depthwise 3x3 fp16 -> fp16
    dw3x3_k<<<N_ * C_, 512>>>(gt, w_dw, dh);
    // 5) y = conv1x1(dw, w_pw) [fp16] + GN2 partials
    gemm_mma<0><<<ggrid, 256, GEMM_SMEM>>>(wh + 2*C_*C_, dh, y16, part2, nullptr, nullptr);
    // 6) out = silu(gn(y)) -> fp32
    gn_silu_out_k<<<N_ * C_, 512>>>(y16, part2, g2, b2, out);
}

// round 14
// speedup vs baseline: 1.0317x; 1.0306x over previous
#include <cuda_runtime.h>
#include <cuda_fp16.h>
#include <math.h>
#include <cstdint>

#define C_ 256
#define G_ 16
#define CPG 16
#define N_ 8
#define H_ 80
#define W_ 80
#define HW 6400
#define CHW (C_*HW)
#define NCHW (N_*C_*HW)
#define EPSV 1e-5f
#define NBLK 50
#define NGTOT (N_*G_)
#define PLW 84   // padded plane row width (floats)

// fp16 tensor planes
__device__ __half g_xh[NCHW];
__device__ __half g_h0[NCHW];
__device__ __half g_hh[NCHW];
__device__ __half g_fu[NCHW];
__device__ __half g_gt[NCHW];
__device__ __half g_dh[NCHW];
__device__ __half g_y[NCHW];
__device__ __half g_wh[3*C_*C_];
__device__ float g_partials1[2 * NGTOT * NBLK];
__device__ float g_partials2[2 * NGTOT * NBLK];

__device__ __forceinline__ uint32_t smem_u32(const void* p) {
    uint32_t a;
    asm("{ .reg .u64 t; cvta.to.shared.u64 t, %1; cvt.u32.u64 %0, t; }"
        : "=r"(a) : "l"(p));
    return a;
}
#define CP_ASYNC16(dst, src) \
    asm volatile("cp.async.cg.shared.global [%0], [%1], 16;" :: "r"(dst), "l"(src))
#define CP_COMMIT() asm volatile("cp.async.commit_group;" ::: "memory")
#define CP_WAIT(n)  asm volatile("cp.async.wait_group %0;" :: "n"(n) : "memory")

// smem: A resident [128 x 264 halfs] = 67584 B, B ring 4 x [32 x 136 halfs]
#define A_STRIDE 264
#define A_BYTES  (128*A_STRIDE*2)
#define B_STRIDE 136
#define B_STAGE  (32*B_STRIDE*2)
#define NSTAGE   4
#define GEMM_SMEM (A_BYTES + NSTAGE*B_STAGE)

__device__ __forceinline__ void ldsm_x4(uint32_t* r, uint32_t addr) {
    asm volatile("ldmatrix.sync.aligned.m8n8.x4.shared.b16 {%0,%1,%2,%3}, [%4];"
        : "=r"(r[0]), "=r"(r[1]), "=r"(r[2]), "=r"(r[3]) : "r"(addr));
}
__device__ __forceinline__ void ldsm_x2t(uint32_t* r, uint32_t addr) {
    asm volatile("ldmatrix.sync.aligned.m8n8.x2.trans.shared.b16 {%0,%1}, [%2];"
        : "=r"(r[0]), "=r"(r[1]) : "r"(addr));
}
__device__ __forceinline__ void mma_f16(float* c, const uint32_t* a, const uint32_t* b) {
    asm volatile(
        "mma.sync.aligned.m16n8k16.row.col.f32.f16.f16.f32 "
        "{%0,%1,%2,%3}, {%4,%5,%6,%7}, {%8,%9}, {%0,%1,%2,%3};"
        : "+f"(c[0]), "+f"(c[1]), "+f"(c[2]), "+f"(c[3])
        : "r"(a[0]), "r"(a[1]), "r"(a[2]), "r"(a[3]), "r"(b[0]), "r"(b[1]));
}
__device__ __forceinline__ float sigm(float v) {
    float t;
    asm("tanh.approx.f32 %0, %1;" : "=f"(t) : "f"(v * 0.5f));
    return fmaf(0.5f, t, 0.5f);
}
// uint4 (8 halfs) <-> 8 floats
__device__ __forceinline__ void unpack8(uint4 pk, float* f) {
    __half2 h0 = *(__half2*)&pk.x, h1 = *(__half2*)&pk.y;
    __half2 h2 = *(__half2*)&pk.z, h3 = *(__half2*)&pk.w;
    float2 a = __half22float2(h0), b = __half22float2(h1);
    float2 c = __half22float2(h2), d = __half22float2(h3);
    f[0] = a.x; f[1] = a.y; f[2] = b.x; f[3] = b.y;
    f[4] = c.x; f[5] = c.y; f[6] = d.x; f[7] = d.y;
}
__device__ __forceinline__ uint4 pack8(const float* f) {
    __half2 h0 = __floats2half2_rn(f[0], f[1]);
    __half2 h1 = __floats2half2_rn(f[2], f[3]);
    __half2 h2 = __floats2half2_rn(f[4], f[5]);
    __half2 h3 = __floats2half2_rn(f[6], f[7]);
    return make_uint4(*(uint32_t*)&h0, *(uint32_t*)&h1,
                      *(uint32_t*)&h2, *(uint32_t*)&h3);
}

__device__ __forceinline__ void issue_b(uint32_t sbase, int tid, int k0, int n0,
                                        const __half* Bx) {
#pragma unroll
    for (int j = 0; j < 2; j++) {
        int i = tid + 256 * j;
        int kk = i >> 4, seg = i & 15;
        uint32_t dst = sbase + (uint32_t)(kk * (B_STRIDE * 2) + seg * 16);
        CP_ASYNC16(dst, Bx + (size_t)(k0 + kk) * HW + n0 + seg * 8);
    }
}

template<int MODE>
__global__ __launch_bounds__(256, 2)
void gemm_mma(const __half* __restrict__ Wh, const __half* __restrict__ Bx,
              __half* __restrict__ Y,
              float* __restrict__ partials,
              const __half* __restrict__ fusedsrc,
              const float* __restrict__ b_gate) {
    extern __shared__ char smem[];
    __shared__ float sred[8][4][2];
    const uint32_t sb = smem_u32(smem);
    const uint32_t bb = sb + A_BYTES;
    const int tid = threadIdx.x;
    const int lane = tid & 31;
    const int w = tid >> 5;
    const int wm = w & 1;
    const int wn = w >> 1;
    const int n0 = blockIdx.x * 128;
    const int m0 = blockIdx.y * 128;
    const __half* Bn = Bx + (size_t)blockIdx.z * CHW;
    __half* Yn = Y + (size_t)blockIdx.z * CHW;

    float acc[4][4][4];
#pragma unroll
    for (int i = 0; i < 4; i++)
#pragma unroll
        for (int j = 0; j < 4; j++)
#pragma unroll
            for (int q = 0; q < 4; q++) acc[i][j][q] = 0.f;

#pragma unroll
    for (int j = 0; j < 16; j++) {
        int i = tid + 256 * j;
        int row = i >> 5, seg = i & 31;
        uint32_t dst = sb + (uint32_t)(row * (A_STRIDE * 2) + seg * 16);
        CP_ASYNC16(dst, Wh + (size_t)(m0 + row) * 256 + seg * 8);
    }
    issue_b(bb, tid, 0, n0, Bn);
    CP_COMMIT();
    issue_b(bb + B_STAGE, tid, 32, n0, Bn);
    CP_COMMIT();
    issue_b(bb + 2 * B_STAGE, tid, 64, n0, Bn);
    CP_COMMIT();

    const uint32_t a_lane_off = (uint32_t)((lane & 15) * A_STRIDE + ((lane >> 4) << 3)) * 2;
    const uint32_t b_lane_off = (uint32_t)((lane & 15) * B_STRIDE) * 2;

    for (int ch = 0; ch < 8; ch++) {
        const int st = ch & 3;
        if (ch < 6) { CP_WAIT(2); } else if (ch == 6) { CP_WAIT(1); } else { CP_WAIT(0); }
        __syncthreads();
        {
            const uint32_t a_chunk = sb + (uint32_t)(wm * 64) * (A_STRIDE * 2)
                                     + a_lane_off + (uint32_t)(ch * 32) * 2;
            const uint32_t SBB = bb + st * B_STAGE;
#pragma unroll
            for (int ks = 0; ks < 2; ks++) {
                const uint32_t kb = (uint32_t)(ks * 16);
                uint32_t ah[4][4], bh[4][2];
#pragma unroll
                for (int mt = 0; mt < 4; mt++) {
                    ldsm_x4(ah[mt], a_chunk + (uint32_t)(mt * 16) * (A_STRIDE * 2) + kb * 2);
                }
#pragma unroll
                for (int nt = 0; nt < 4; nt++) {
                    ldsm_x2t(bh[nt], SBB + b_lane_off + kb * (B_STRIDE * 2)
                                     + (uint32_t)(wn * 32 + nt * 8) * 2);
                }
#pragma unroll
                for (int mt = 0; mt < 4; mt++)
#pragma unroll
                    for (int nt = 0; nt < 4; nt++)
                        mma_f16(acc[mt][nt], ah[mt], bh[nt]);
            }
        }
        if (ch < 5) {
            issue_b(bb + ((ch + 3) & 3) * B_STAGE, tid, (ch + 3) * 32, n0, Bn);
            CP_COMMIT();
        }
    }

    if (MODE == 0) {
        float s[4], s2[4];
#pragma unroll
        for (int mt = 0; mt < 4; mt++) { s[mt] = 0.f; s2[mt] = 0.f; }
#pragma unroll
        for (int mt = 0; mt < 4; mt++) {
            const int r = m0 + wm * 64 + mt * 16 + (lane >> 2);
#pragma unroll
            for (int nt = 0; nt < 4; nt++) {
                const int cc = n0 + wn * 32 + nt * 8 + (lane & 3) * 2;
                __half2 p01 = __floats2half2_rn(acc[mt][nt][0], acc[mt][nt][1]);
                __half2 p23 = __floats2half2_rn(acc[mt][nt][2], acc[mt][nt][3]);
                *(__half2*)(Yn + (size_t)r * HW + cc) = p01;
                *(__half2*)(Yn + (size_t)(r + 8) * HW + cc) = p23;
#pragma unroll
                for (int q = 0; q < 4; q++) {
                    float v = acc[mt][nt][q];
                    s[mt] += v; s2[mt] += v * v;
                }
            }
        }
#pragma unroll
        for (int mt = 0; mt < 4; mt++) {
#pragma unroll
            for (int off = 16; off > 0; off >>= 1) {
                s[mt]  += __shfl_down_sync(0xFFFFFFFFu, s[mt], off);
                s2[mt] += __shfl_down_sync(0xFFFFFFFFu, s2[mt], off);
            }
        }
        __syncthreads();
        if (lane == 0) {
#pragma unroll
            for (int mt = 0; mt < 4; mt++) {
                sred[w][mt][0] = s[mt];
                sred[w][mt][1] = s2[mt];
            }
        }
        __syncthreads();
        if (tid < 8) {
            const int twm = tid >> 2, tmt = tid & 3;
            float S = 0.f, S2 = 0.f;
#pragma unroll
            for (int j = 0; j < 4; j++) {
                S  += sred[twm + 2 * j][tmt][0];
                S2 += sred[twm + 2 * j][tmt][1];
            }
            const int g = blockIdx.y * 8 + twm * 4 + tmt;
            const int ng = blockIdx.z * G_ + g;
            partials[ng * NBLK + blockIdx.x] = S;
            partials[NGTOT * NBLK + ng * NBLK + blockIdx.x] = S2;
        }
    } else {
        const __half* fn = fusedsrc + (size_t)blockIdx.z * CHW;
#pragma unroll
        for (int mt = 0; mt < 4; mt++) {
            const int r0 = m0 + wm * 64 + mt * 16 + (lane >> 2);
#pragma unroll
            for (int nt = 0; nt < 4; nt++) {
                const int cc = n0 + wn * 32 + nt * 8 + (lane & 3) * 2;
#pragma unroll
                for (int half = 0; half < 2; half++) {
                    const int r = r0 + half * 8;
                    const float bg = b_gate[r];
                    float2 fv = __half22float2(*(const __half2*)(fn + (size_t)r * HW + cc));
                    float o0 = fv.x * sigm(acc[mt][nt][half * 2 + 0] + bg);
                    float o1 = fv.y * sigm(acc[mt][nt][half * 2 + 1] + bg);
                    *(__half2*)(Yn + (size_t)r * HW + cc) = __floats2half2_rn(o0, o1);
                }
            }
        }
    }
}

// ---------------------------------------------------------------------------
// fp32 -> fp16, 8 floats per thread
// ---------------------------------------------------------------------------
__global__ void cvt_x_k(const float* __restrict__ in, __half* __restrict__ o, int n8) {
    int i = blockIdx.x * 256 + threadIdx.x;
    if (i >= n8) return;
    float f[8];
    *(float4*)(f)     = *(const float4*)(in + i * 8);
    *(float4*)(f + 4) = *(const float4*)(in + i * 8 + 4);
    *(uint4*)(o + i * 8) = pack8(f);
}
__global__ void cvt_w3_k(const float* __restrict__ w0, const float* __restrict__ w1,
                         const float* __restrict__ w2, __half* __restrict__ o) {
    const float* src = (blockIdx.y == 0) ? w0 : (blockIdx.y == 1) ? w1 : w2;
    __half* dst = o + (size_t)blockIdx.y * C_ * C_;
    int i = blockIdx.x * 256 + threadIdx.x;
    float f[8];
    *(float4*)(f)     = *(const float4*)(src + i * 8);
    *(float4*)(f + 4) = *(const float4*)(src + i * 8 + 4);
    *(uint4*)(dst + i * 8) = pack8(f);
}

// ---------------------------------------------------------------------------
__device__ __forceinline__ void block_stats(const float* __restrict__ partials,
                                            int ng, int tid, float* smr,
                                            float& mean, float& rstd) {
    if (tid < 32) {
        float s = 0.f, s2 = 0.f;
        for (int i = tid; i < NBLK; i += 32) {
            s  += partials[ng * NBLK + i];
            s2 += partials[NGTOT * NBLK + ng * NBLK + i];
        }
#pragma unroll
        for (int off = 16; off > 0; off >>= 1) {
            s  += __shfl_down_sync(0xFFFFFFFFu, s, off);
            s2 += __shfl_down_sync(0xFFFFFFFFu, s2, off);
        }
        if (tid == 0) {
            const float M = (float)(CPG * HW);
            float mu = s / M;
            float var = s2 / M - mu * mu;
            smr[0] = mu;
            smr[1] = rsqrtf(var + EPSV);
        }
    }
    __syncthreads();
    mean = smr[0];
    rstd = smr[1];
}

// ---------------------------------------------------------------------------
// GN + SiLU + fused. 16B vectorized I/O, padded fp32 smem plane.
// ---------------------------------------------------------------------------
__global__ __launch_bounds__(256)
void gn_silu_rowcol_k(const __half* __restrict__ H0,
                      const float* __restrict__ partials,
                      const float* __restrict__ gamma,
                      const float* __restrict__ beta,
                      __half* __restrict__ Hh,
                      __half* __restrict__ F) {
    __shared__ float plane[H_ * PLW];
    __shared__ float rs[H_], cs[W_];
    __shared__ float smr[2];
    const int nc = blockIdx.x;
    const int c = nc & (C_ - 1);
    const int ng = (nc >> 8) * G_ + (c >> 4);
    const int tid = threadIdx.x;
    float mean, rstd;
    block_stats(partials, ng, tid, smr, mean, rstd);
    const float ga = gamma[c];
    const float be = beta[c];
    const __half* base = H0 + (size_t)nc * HW;
    __half* hh = Hh + (size_t)nc * HW;
    __half* fb = F + (size_t)nc * HW;

    for (int i = tid; i < HW / 8; i += 256) {
        const int p0 = i * 8;
        const int y = p0 / W_;
        const int x = p0 - y * W_;
        float f[8];
        unpack8(*(const uint4*)(base + p0), f);
#pragma unroll
        for (int e = 0; e < 8; e++) {
            float v = (f[e] - mean) * rstd * ga + be;
            f[e] = v * sigm(v);
        }
        float* pp = plane + y * PLW + x;
        *(float4*)(pp)     = *(float4*)(f);
        *(float4*)(pp + 4) = *(float4*)(f + 4);
        *(uint4*)(hh + p0) = pack8(f);
    }
    __syncthreads();
    if (tid < H_) {
        const int y = tid;
        const float4* rp = (const float4*)(plane + y * PLW);
        float s = 0.f;
#pragma unroll
        for (int j = 0; j < 20; j++) {
            float4 v = rp[j];
            s += v.x + v.y + v.z + v.w;
        }
        rs[y] = s;
    } else if (tid < H_ + W_) {
        const int x = tid - H_;
        float s = 0.f;
#pragma unroll 8
        for (int y = 0; y < H_; y++) s += plane[y * PLW + x];
        cs[x] = s;
    }
    __syncthreads();
    for (int i = tid; i < HW / 8; i += 256) {
        const int p0 = i * 8;
        const int y = p0 / W_;
        const int x = p0 - y * W_;
        const float* pp = plane + y * PLW + x;
        const float ry = rs[y];
        float f[8];
        *(float4*)(f)     = *(const float4*)(pp);
        *(float4*)(f + 4) = *(const float4*)(pp + 4);
#pragma unroll
        for (int e = 0; e < 8; e++)
            f[e] = 0.25f * (ry + cs[x + e] + 2.f * f[e]);
        *(uint4*)(fb + p0) = pack8(f);
    }
}

// ---------------------------------------------------------------------------
// depthwise 3x3 — 16B vectorized I/O; 8 outputs per iter, 30 LDS per iter
// ---------------------------------------------------------------------------
__global__ __launch_bounds__(256)
void dw3x3_k(const __half* __restrict__ in,
             const float* __restrict__ wdw,
             __half* __restrict__ Oh) {
    __shared__ float pl[H_ * PLW];
    const int nc = blockIdx.x;
    const int c = nc & (C_ - 1);
    float wr[9];
#pragma unroll
    for (int q = 0; q < 9; q++) wr[q] = __ldg(wdw + c * 9 + q);
    const __half* p = in + (size_t)nc * HW;
    __half* oh = Oh + (size_t)nc * HW;
    for (int i = threadIdx.x; i < HW / 8; i += 256) {
        const int p0 = i * 8;
        const int y = p0 / W_;
        const int x = p0 - y * W_;
        float f[8];
        unpack8(*(const uint4*)(p + p0), f);
        float* pp = pl + y * PLW + x;
        *(float4*)(pp)     = *(float4*)(f);
        *(float4*)(pp + 4) = *(float4*)(f + 4);
    }
    __syncthreads();
    for (int i = threadIdx.x; i < HW / 8; i += 256) {
        const int p0 = i * 8;
        const int y = p0 / W_;
        const int x0 = p0 - y * W_;
        float o[8];
#pragma unroll
        for (int e = 0; e < 8; e++) o[e] = 0.f;
#pragma unroll
        for (int dy = -1; dy <= 1; dy++) {
            const int yy = y + dy;
            if ((unsigned)yy >= H_) continue;
            const float* rp = pl + yy * PLW;
            float t[10];
#pragma unroll
            for (int j = 0; j < 10; j++) {
                const int xx = x0 - 1 + j;
                t[j] = ((unsigned)xx < W_) ? rp[xx] : 0.f;
            }
            const float w0 = wr[(dy + 1) * 3], w1 = wr[(dy + 1) * 3 + 1], w2 = wr[(dy + 1) * 3 + 2];
#pragma unroll
            for (int e = 0; e < 8; e++)
                o[e] += w0 * t[e] + w1 * t[e + 1] + w2 * t[e + 2];
        }
        *(uint4*)(oh + p0) = pack8(o);
    }
}

// ---------------------------------------------------------------------------
// final: out = silu(gn(y)), vectorized
// ---------------------------------------------------------------------------
__global__ __launch_bounds__(256)
void gn_silu_out_k(const __half* __restrict__ Yin,
                   const float* __restrict__ partials,
                   const float* __restrict__ gamma,
                   const float* __restrict__ beta,
                   float* __restrict__ out) {
    __shared__ float smr[2];
    const int nc = blockIdx.x;
    const int c = nc & (C_ - 1);
    const int ng = (nc >> 8) * G_ + (c >> 4);
    const int tid = threadIdx.x;
    float mean, rstd;
    block_stats(partials, ng, tid, smr, mean, rstd);
    const float ga = gamma[c];
    const float be = beta[c];
    const __half* yp = Yin + (size_t)nc * HW;
    float* op = out + (size_t)nc * HW;
    for (int i = tid; i < HW / 8; i += 256) {
        const int p0 = i * 8;
        float f[8];
        unpack8(*(const uint4*)(yp + p0), f);
#pragma unroll
        for (int e = 0; e < 8; e++) {
            float v = (f[e] - mean) * rstd * ga + be;
            f[e] = v * sigm(v);
        }
        *(float4*)(op + p0)     = *(float4*)(f);
        *(float4*)(op + p0 + 4) = *(float4*)(f + 4);
    }
}

// ---------------------------------------------------------------------------
extern "C" void kernel_launch(void* const* d_in, const int* in_sizes, int n_in,
                              void* d_out, int out_size) {
    const float* x      = (const float*)d_in[0];
    const float* w_pre  = (const float*)d_in[1];
    const float* g1     = (const float*)d_in[2];
    const float* b1     = (const float*)d_in[3];
    const float* w_gate = (const float*)d_in[4];
    const float* b_gate = (const float*)d_in[5];
    const float* w_dw   = (const float*)d_in[6];
    const float* w_pw   = (const float*)d_in[7];
    const float* g2     = (const float*)d_in[8];
    const float* b2     = (const float*)d_in[9];
    float* out = (float*)d_out;

    float *part1, *part2;
    __half *xh, *h0, *hh, *fu, *gt, *dh, *y16, *wh;
    cudaGetSymbolAddress((void**)&part1, g_partials1);
    cudaGetSymbolAddress((void**)&part2, g_partials2);
    cudaGetSymbolAddress((void**)&xh, g_xh);
    cudaGetSymbolAddress((void**)&h0, g_h0);
    cudaGetSymbolAddress((void**)&hh, g_hh);
    cudaGetSymbolAddress((void**)&fu, g_fu);
    cudaGetSymbolAddress((void**)&gt, g_gt);
    cudaGetSymbolAddress((void**)&dh, g_dh);
    cudaGetSymbolAddress((void**)&y16, g_y);
    cudaGetSymbolAddress((void**)&wh, g_wh);

    cudaFuncSetAttribute(gemm_mma<0>, cudaFuncAttributeMaxDynamicSharedMemorySize, GEMM_SMEM);
    cudaFuncSetAttribute(gemm_mma<1>, cudaFuncAttributeMaxDynamicSharedMemorySize, GEMM_SMEM);

    dim3 ggrid(NBLK, 2, N_);

    // 0) operand conversion
    cvt_w3_k<<<dim3(C_*C_/8/256, 3), 256>>>(w_pre, w_gate, w_pw, wh);
    cvt_x_k<<<NCHW/8/256, 256>>>(x, xh, NCHW/8);

    // 1) h0 = conv1x1(x, w_pre) [fp16] + GN1 partials
    gemm_mma<0><<<ggrid, 256, GEMM_SMEM>>>(wh, xh, h0, part1, nullptr, nullptr);
    // 2) h = silu(gn(h0)) -> fp16 + fused -> fp16
    gn_silu_rowcol_k<<<N_ * C_, 256>>>(h0, part1, g1, b1, hh, fu);
    // 3) gated = fused * sigmoid(conv1x1(h,w_gate)+b) -> fp16
    gemm_mma<1><<<ggrid, 256, GEMM_SMEM>>>(wh + C_*C_, hh, gt, nullptr, fu, b_gate);
    // 4) depthwise 3x3 fp16 -> fp16
    dw3x3_k<<<N_ * C_, 256>>>(gt, w_dw, dh);
    // 5) y = conv1x1(dw, w_pw) [fp16] + GN2 partials
    gemm_mma<0><<<ggrid, 256, GEMM_SMEM>>>(wh + 2*C_*C_, dh, y16, part2, nullptr, nullptr);
    // 6) out = silu(gn(y)) -> fp32
    gn_silu_out_k<<<N_ * C_, 256>>>(y16, part2, g2, b2, out);
}

// round 15
// speedup vs baseline: 1.0416x; 1.0096x over previous
#include <cuda_runtime.h>
#include <cuda_fp16.h>
#include <math.h>
#include <cstdint>

#define C_ 256
#define G_ 16
#define CPG 16
#define N_ 8
#define H_ 80
#define W_ 80
#define HW 6400
#define CHW (C_*HW)
#define NCHW (N_*C_*HW)
#define EPSV 1e-5f
#define NBLK 50
#define NGTOT (N_*G_)
#define PLW 84   // padded plane row width (floats)

// fp16 tensor planes
__device__ __half g_xh[NCHW];
__device__ __half g_h0[NCHW];
__device__ __half g_hh[NCHW];
__device__ __half g_fu[NCHW];
__device__ __half g_gt[NCHW];
__device__ __half g_dh[NCHW];
__device__ __half g_y[NCHW];
__device__ __half g_wh[3*C_*C_];
__device__ float g_partials1[2 * NGTOT * NBLK];
__device__ float g_partials2[2 * NGTOT * NBLK];

__device__ __forceinline__ uint32_t smem_u32(const void* p) {
    uint32_t a;
    asm("{ .reg .u64 t; cvta.to.shared.u64 t, %1; cvt.u32.u64 %0, t; }"
        : "=r"(a) : "l"(p));
    return a;
}
#define CP_ASYNC16(dst, src) \
    asm volatile("cp.async.cg.shared.global [%0], [%1], 16;" :: "r"(dst), "l"(src))
#define CP_COMMIT() asm volatile("cp.async.commit_group;" ::: "memory")
#define CP_WAIT(n)  asm volatile("cp.async.wait_group %0;" :: "n"(n) : "memory")

// smem: A resident [128 x 264 halfs] = 67584 B, B ring 4 x [32 x 136 halfs]
#define A_STRIDE 264
#define A_BYTES  (128*A_STRIDE*2)
#define B_STRIDE 136
#define B_STAGE  (32*B_STRIDE*2)
#define NSTAGE   4
#define GEMM_SMEM (A_BYTES + NSTAGE*B_STAGE)

__device__ __forceinline__ void ldsm_x4(uint32_t* r, uint32_t addr) {
    asm volatile("ldmatrix.sync.aligned.m8n8.x4.shared.b16 {%0,%1,%2,%3}, [%4];"
        : "=r"(r[0]), "=r"(r[1]), "=r"(r[2]), "=r"(r[3]) : "r"(addr));
}
__device__ __forceinline__ void ldsm_x4t(uint32_t* r, uint32_t addr) {
    asm volatile("ldmatrix.sync.aligned.m8n8.x4.trans.shared.b16 {%0,%1,%2,%3}, [%4];"
        : "=r"(r[0]), "=r"(r[1]), "=r"(r[2]), "=r"(r[3]) : "r"(addr));
}
__device__ __forceinline__ void mma_f16(float* c, const uint32_t* a, const uint32_t* b) {
    asm volatile(
        "mma.sync.aligned.m16n8k16.row.col.f32.f16.f16.f32 "
        "{%0,%1,%2,%3}, {%4,%5,%6,%7}, {%8,%9}, {%0,%1,%2,%3};"
        : "+f"(c[0]), "+f"(c[1]), "+f"(c[2]), "+f"(c[3])
        : "r"(a[0]), "r"(a[1]), "r"(a[2]), "r"(a[3]), "r"(b[0]), "r"(b[1]));
}
__device__ __forceinline__ float sigm(float v) {
    float t;
    asm("tanh.approx.f32 %0, %1;" : "=f"(t) : "f"(v * 0.5f));
    return fmaf(0.5f, t, 0.5f);
}
// uint4 (8 halfs) <-> 8 floats
__device__ __forceinline__ void unpack8(uint4 pk, float* f) {
    __half2 h0 = *(__half2*)&pk.x, h1 = *(__half2*)&pk.y;
    __half2 h2 = *(__half2*)&pk.z, h3 = *(__half2*)&pk.w;
    float2 a = __half22float2(h0), b = __half22float2(h1);
    float2 c = __half22float2(h2), d = __half22float2(h3);
    f[0] = a.x; f[1] = a.y; f[2] = b.x; f[3] = b.y;
    f[4] = c.x; f[5] = c.y; f[6] = d.x; f[7] = d.y;
}
__device__ __forceinline__ uint4 pack8(const float* f) {
    __half2 h0 = __floats2half2_rn(f[0], f[1]);
    __half2 h1 = __floats2half2_rn(f[2], f[3]);
    __half2 h2 = __floats2half2_rn(f[4], f[5]);
    __half2 h3 = __floats2half2_rn(f[6], f[7]);
    return make_uint4(*(uint32_t*)&h0, *(uint32_t*)&h1,
                      *(uint32_t*)&h2, *(uint32_t*)&h3);
}

__device__ __forceinline__ void issue_b(uint32_t sbase, int tid, int k0, int n0,
                                        const __half* Bx) {
#pragma unroll
    for (int j = 0; j < 2; j++) {
        int i = tid + 256 * j;
        int kk = i >> 4, seg = i & 15;
        uint32_t dst = sbase + (uint32_t)(kk * (B_STRIDE * 2) + seg * 16);
        CP_ASYNC16(dst, Bx + (size_t)(k0 + kk) * HW + n0 + seg * 8);
    }
}

template<int MODE>
__global__ __launch_bounds__(256, 2)
void gemm_mma(const __half* __restrict__ Wh, const __half* __restrict__ Bx,
              __half* __restrict__ Y,
              float* __restrict__ partials,
              const __half* __restrict__ fusedsrc,
              const float* __restrict__ b_gate) {
    extern __shared__ char smem[];
    __shared__ float sred[8][4][2];
    const uint32_t sb = smem_u32(smem);
    const uint32_t bb = sb + A_BYTES;
    const int tid = threadIdx.x;
    const int lane = tid & 31;
    const int w = tid >> 5;
    const int wm = w & 1;
    const int wn = w >> 1;
    const int n0 = blockIdx.x * 128;
    const int m0 = blockIdx.y * 128;
    const __half* Bn = Bx + (size_t)blockIdx.z * CHW;
    __half* Yn = Y + (size_t)blockIdx.z * CHW;

    float acc[4][4][4];
#pragma unroll
    for (int i = 0; i < 4; i++)
#pragma unroll
        for (int j = 0; j < 4; j++)
#pragma unroll
            for (int q = 0; q < 4; q++) acc[i][j][q] = 0.f;

#pragma unroll
    for (int j = 0; j < 16; j++) {
        int i = tid + 256 * j;
        int row = i >> 5, seg = i & 31;
        uint32_t dst = sb + (uint32_t)(row * (A_STRIDE * 2) + seg * 16);
        CP_ASYNC16(dst, Wh + (size_t)(m0 + row) * 256 + seg * 8);
    }
    issue_b(bb, tid, 0, n0, Bn);
    CP_COMMIT();
    issue_b(bb + B_STAGE, tid, 32, n0, Bn);
    CP_COMMIT();
    issue_b(bb + 2 * B_STAGE, tid, 64, n0, Bn);
    CP_COMMIT();

    const uint32_t a_lane_off = (uint32_t)((lane & 15) * A_STRIDE + ((lane >> 4) << 3)) * 2;
    // x4-trans B addressing: lanes 0-15 -> n-block 0 (k rows 0..15),
    // lanes 16-31 -> n-block +8 (k rows 0..15)
    const uint32_t b4_lane_off = (uint32_t)((lane & 15) * B_STRIDE + (lane >> 4) * 8) * 2;

    for (int ch = 0; ch < 8; ch++) {
        const int st = ch & 3;
        if (ch < 6) { CP_WAIT(2); } else if (ch == 6) { CP_WAIT(1); } else { CP_WAIT(0); }
        __syncthreads();
        {
            const uint32_t a_chunk = sb + (uint32_t)(wm * 64) * (A_STRIDE * 2)
                                     + a_lane_off + (uint32_t)(ch * 32) * 2;
            const uint32_t SBB = bb + st * B_STAGE;
#pragma unroll
            for (int ks = 0; ks < 2; ks++) {
                const uint32_t kb = (uint32_t)(ks * 16);
                uint32_t ah[4][4], bh[2][4];
#pragma unroll
                for (int g = 0; g < 2; g++) {
                    ldsm_x4t(bh[g], SBB + b4_lane_off + kb * (B_STRIDE * 2)
                                    + (uint32_t)(wn * 32 + g * 16) * 2);
                }
#pragma unroll
                for (int mt = 0; mt < 4; mt++) {
                    ldsm_x4(ah[mt], a_chunk + (uint32_t)(mt * 16) * (A_STRIDE * 2) + kb * 2);
                }
#pragma unroll
                for (int mt = 0; mt < 4; mt++)
#pragma unroll
                    for (int g = 0; g < 2; g++) {
                        mma_f16(acc[mt][2 * g],     ah[mt], bh[g]);
                        mma_f16(acc[mt][2 * g + 1], ah[mt], bh[g] + 2);
                    }
            }
        }
        if (ch < 5) {
            issue_b(bb + ((ch + 3) & 3) * B_STAGE, tid, (ch + 3) * 32, n0, Bn);
            CP_COMMIT();
        }
    }

    if (MODE == 0) {
        float s[4], s2[4];
#pragma unroll
        for (int mt = 0; mt < 4; mt++) { s[mt] = 0.f; s2[mt] = 0.f; }
#pragma unroll
        for (int mt = 0; mt < 4; mt++) {
            const int r = m0 + wm * 64 + mt * 16 + (lane >> 2);
#pragma unroll
            for (int nt = 0; nt < 4; nt++) {
                const int cc = n0 + wn * 32 + nt * 8 + (lane & 3) * 2;
                __half2 p01 = __floats2half2_rn(acc[mt][nt][0], acc[mt][nt][1]);
                __half2 p23 = __floats2half2_rn(acc[mt][nt][2], acc[mt][nt][3]);
                *(__half2*)(Yn + (size_t)r * HW + cc) = p01;
                *(__half2*)(Yn + (size_t)(r + 8) * HW + cc) = p23;
#pragma unroll
                for (int q = 0; q < 4; q++) {
                    float v = acc[mt][nt][q];
                    s[mt] += v; s2[mt] += v * v;
                }
            }
        }
#pragma unroll
        for (int mt = 0; mt < 4; mt++) {
#pragma unroll
            for (int off = 16; off > 0; off >>= 1) {
                s[mt]  += __shfl_down_sync(0xFFFFFFFFu, s[mt], off);
                s2[mt] += __shfl_down_sync(0xFFFFFFFFu, s2[mt], off);
            }
        }
        __syncthreads();
        if (lane == 0) {
#pragma unroll
            for (int mt = 0; mt < 4; mt++) {
                sred[w][mt][0] = s[mt];
                sred[w][mt][1] = s2[mt];
            }
        }
        __syncthreads();
        if (tid < 8) {
            const int twm = tid >> 2, tmt = tid & 3;
            float S = 0.f, S2 = 0.f;
#pragma unroll
            for (int j = 0; j < 4; j++) {
                S  += sred[twm + 2 * j][tmt][0];
                S2 += sred[twm + 2 * j][tmt][1];
            }
            const int g = blockIdx.y * 8 + twm * 4 + tmt;
            const int ng = blockIdx.z * G_ + g;
            partials[ng * NBLK + blockIdx.x] = S;
            partials[NGTOT * NBLK + ng * NBLK + blockIdx.x] = S2;
        }
    } else {
        const __half* fn = fusedsrc + (size_t)blockIdx.z * CHW;
#pragma unroll
        for (int mt = 0; mt < 4; mt++) {
            const int r0 = m0 + wm * 64 + mt * 16 + (lane >> 2);
#pragma unroll
            for (int nt = 0; nt < 4; nt++) {
                const int cc = n0 + wn * 32 + nt * 8 + (lane & 3) * 2;
#pragma unroll
                for (int half = 0; half < 2; half++) {
                    const int r = r0 + half * 8;
                    const float bg = b_gate[r];
                    float2 fv = __half22float2(*(const __half2*)(fn + (size_t)r * HW + cc));
                    float o0 = fv.x * sigm(acc[mt][nt][half * 2 + 0] + bg);
                    float o1 = fv.y * sigm(acc[mt][nt][half * 2 + 1] + bg);
                    *(__half2*)(Yn + (size_t)r * HW + cc) = __floats2half2_rn(o0, o1);
                }
            }
        }
    }
}

// ---------------------------------------------------------------------------
// combined fp32 -> fp16 conversion: x (blocks 0..6399) + 3 weights (96 blocks)
// ---------------------------------------------------------------------------
#define XBLK (NCHW/8/256)          // 6400
#define WBLK_PER (C_*C_/8/256)     // 32
__global__ void cvt_all_k(const float* __restrict__ x,
                          const float* __restrict__ w0,
                          const float* __restrict__ w1,
                          const float* __restrict__ w2,
                          __half* __restrict__ xh, __half* __restrict__ wh) {
    const int b = blockIdx.x;
    const float* src;
    __half* dst;
    int i;
    if (b < XBLK) {
        src = x; dst = xh;
        i = b * 256 + threadIdx.x;
    } else {
        const int t = (b - XBLK) / WBLK_PER;       // which weight tensor
        src = (t == 0) ? w0 : (t == 1) ? w1 : w2;
        dst = wh + (size_t)t * C_ * C_;
        i = ((b - XBLK) % WBLK_PER) * 256 + threadIdx.x;
    }
    float f[8];
    *(float4*)(f)     = *(const float4*)(src + i * 8);
    *(float4*)(f + 4) = *(const float4*)(src + i * 8 + 4);
    *(uint4*)(dst + i * 8) = pack8(f);
}

// ---------------------------------------------------------------------------
__device__ __forceinline__ void block_stats(const float* __restrict__ partials,
                                            int ng, int tid, float* smr,
                                            float& mean, float& rstd) {
    if (tid < 32) {
        float s = 0.f, s2 = 0.f;
        for (int i = tid; i < NBLK; i += 32) {
            s  += partials[ng * NBLK + i];
            s2 += partials[NGTOT * NBLK + ng * NBLK + i];
        }
#pragma unroll
        for (int off = 16; off > 0; off >>= 1) {
            s  += __shfl_down_sync(0xFFFFFFFFu, s, off);
            s2 += __shfl_down_sync(0xFFFFFFFFu, s2, off);
        }
        if (tid == 0) {
            const float M = (float)(CPG * HW);
            float mu = s / M;
            float var = s2 / M - mu * mu;
            smr[0] = mu;
            smr[1] = rsqrtf(var + EPSV);
        }
    }
    __syncthreads();
    mean = smr[0];
    rstd = smr[1];
}

// ---------------------------------------------------------------------------
// GN + SiLU + fused. 16B vectorized I/O, padded fp32 smem plane.
// ---------------------------------------------------------------------------
__global__ __launch_bounds__(256)
void gn_silu_rowcol_k(const __half* __restrict__ H0,
                      const float* __restrict__ partials,
                      const float* __restrict__ gamma,
                      const float* __restrict__ beta,
                      __half* __restrict__ Hh,
                      __half* __restrict__ F) {
    __shared__ float plane[H_ * PLW];
    __shared__ float rs[H_], cs[W_];
    __shared__ float smr[2];
    const int nc = blockIdx.x;
    const int c = nc & (C_ - 1);
    const int ng = (nc >> 8) * G_ + (c >> 4);
    const int tid = threadIdx.x;
    float mean, rstd;
    block_stats(partials, ng, tid, smr, mean, rstd);
    const float ga = gamma[c];
    const float be = beta[c];
    const __half* base = H0 + (size_t)nc * HW;
    __half* hh = Hh + (size_t)nc * HW;
    __half* fb = F + (size_t)nc * HW;

    for (int i = tid; i < HW / 8; i += 256) {
        const int p0 = i * 8;
        const int y = p0 / W_;
        const int x = p0 - y * W_;
        float f[8];
        unpack8(*(const uint4*)(base + p0), f);
#pragma unroll
        for (int e = 0; e < 8; e++) {
            float v = (f[e] - mean) * rstd * ga + be;
            f[e] = v * sigm(v);
        }
        float* pp = plane + y * PLW + x;
        *(float4*)(pp)     = *(float4*)(f);
        *(float4*)(pp + 4) = *(float4*)(f + 4);
        *(uint4*)(hh + p0) = pack8(f);
    }
    __syncthreads();
    if (tid < H_) {
        const int y = tid;
        const float4* rp = (const float4*)(plane + y * PLW);
        float s = 0.f;
#pragma unroll
        for (int j = 0; j < 20; j++) {
            float4 v = rp[j];
            s += v.x + v.y + v.z + v.w;
        }
        rs[y] = s;
    } else if (tid < H_ + W_) {
        const int x = tid - H_;
        float s = 0.f;
#pragma unroll 8
        for (int y = 0; y < H_; y++) s += plane[y * PLW + x];
        cs[x] = s;
    }
    __syncthreads();
    for (int i = tid; i < HW / 8; i += 256) {
        const int p0 = i * 8;
        const int y = p0 / W_;
        const int x = p0 - y * W_;
        const float* pp = plane + y * PLW + x;
        const float ry = rs[y];
        float f[8];
        *(float4*)(f)     = *(const float4*)(pp);
        *(float4*)(f + 4) = *(const float4*)(pp + 4);
#pragma unroll
        for (int e = 0; e < 8; e++)
            f[e] = 0.25f * (ry + cs[x + e] + 2.f * f[e]);
        *(uint4*)(fb + p0) = pack8(f);
    }
}

// ---------------------------------------------------------------------------
// depthwise 3x3 — 16B vectorized I/O; 8 outputs per iter
// ---------------------------------------------------------------------------
__global__ __launch_bounds__(256)
void dw3x3_k(const __half* __restrict__ in,
             const float* __restrict__ wdw,
             __half* __restrict__ Oh) {
    __shared__ float pl[H_ * PLW];
    const int nc = blockIdx.x;
    const int c = nc & (C_ - 1);
    float wr[9];
#pragma unroll
    for (int q = 0; q < 9; q++) wr[q] = __ldg(wdw + c * 9 + q);
    const __half* p = in + (size_t)nc * HW;
    __half* oh = Oh + (size_t)nc * HW;
    for (int i = threadIdx.x; i < HW / 8; i += 256) {
        const int p0 = i * 8;
        const int y = p0 / W_;
        const int x = p0 - y * W_;
        float f[8];
        unpack8(*(const uint4*)(p + p0), f);
        float* pp = pl + y * PLW + x;
        *(float4*)(pp)     = *(float4*)(f);
        *(float4*)(pp + 4) = *(float4*)(f + 4);
    }
    __syncthreads();
    for (int i = threadIdx.x; i < HW / 8; i += 256) {
        const int p0 = i * 8;
        const int y = p0 / W_;
        const int x0 = p0 - y * W_;
        float o[8];
#pragma unroll
        for (int e = 0; e < 8; e++) o[e] = 0.f;
#pragma unroll
        for (int dy = -1; dy <= 1; dy++) {
            const int yy = y + dy;
            if ((unsigned)yy >= H_) continue;
            const float* rp = pl + yy * PLW;
            float t[10];
#pragma unroll
            for (int j = 0; j < 10; j++) {
                const int xx = x0 - 1 + j;
                t[j] = ((unsigned)xx < W_) ? rp[xx] : 0.f;
            }
            const float w0 = wr[(dy + 1) * 3], w1 = wr[(dy + 1) * 3 + 1], w2 = wr[(dy + 1) * 3 + 2];
#pragma unroll
            for (int e = 0; e < 8; e++)
                o[e] += w0 * t[e] + w1 * t[e + 1] + w2 * t[e + 2];
        }
        *(uint4*)(oh + p0) = pack8(o);
    }
}

// ---------------------------------------------------------------------------
// final: out = silu(gn(y)), vectorized
// ---------------------------------------------------------------------------
__global__ __launch_bounds__(256)
void gn_silu_out_k(const __half* __restrict__ Yin,
                   const float* __restrict__ partials,
                   const float* __restrict__ gamma,
                   const float* __restrict__ beta,
                   float* __restrict__ out) {
    __shared__ float smr[2];
    const int nc = blockIdx.x;
    const int c = nc & (C_ - 1);
    const int ng = (nc >> 8) * G_ + (c >> 4);
    const int tid = threadIdx.x;
    float mean, rstd;
    block_stats(partials, ng, tid, smr, mean, rstd);
    const float ga = gamma[c];
    const float be = beta[c];
    const __half* yp = Yin + (size_t)nc * HW;
    float* op = out + (size_t)nc * HW;
    for (int i = tid; i < HW / 8; i += 256) {
        const int p0 = i * 8;
        float f[8];
        unpack8(*(const uint4*)(yp + p0), f);
#pragma unroll
        for (int e = 0; e < 8; e++) {
            float v = (f[e] - mean) * rstd * ga + be;
            f[e] = v * sigm(v);
        }
        *(float4*)(op + p0)     = *(float4*)(f);
        *(float4*)(op + p0 + 4) = *(float4*)(f + 4);
    }
}

// ---------------------------------------------------------------------------
extern "C" void kernel_launch(void* const* d_in, const int* in_sizes, int n_in,
                              void* d_out, int out_size) {
    const float* x      = (const float*)d_in[0];
    const float* w_pre  = (const float*)d_in[1];
    const float* g1     = (const float*)d_in[2];
    const float* b1     = (const float*)d_in[3];
    const float* w_gate = (const float*)d_in[4];
    const float* b_gate = (const float*)d_in[5];
    const float* w_dw   = (const float*)d_in[6];
    const float* w_pw   = (const float*)d_in[7];
    const float* g2     = (const float*)d_in[8];
    const float* b2     = (const float*)d_in[9];
    float* out = (float*)d_out;

    float *part1, *part2;
    __half *xh, *h0, *hh, *fu, *gt, *dh, *y16, *wh;
    cudaGetSymbolAddress((void**)&part1, g_partials1);
    cudaGetSymbolAddress((void**)&part2, g_partials2);
    cudaGetSymbolAddress((void**)&xh, g_xh);
    cudaGetSymbolAddress((void**)&h0, g_h0);
    cudaGetSymbolAddress((void**)&hh, g_hh);
    cudaGetSymbolAddress((void**)&fu, g_fu);
    cudaGetSymbolAddress((void**)&gt, g_gt);
    cudaGetSymbolAddress((void**)&dh, g_dh);
    cudaGetSymbolAddress((void**)&y16, g_y);
    cudaGetSymbolAddress((void**)&wh, g_wh);

    cudaFuncSetAttribute(gemm_mma<0>, cudaFuncAttributeMaxDynamicSharedMemorySize, GEMM_SMEM);
    cudaFuncSetAttribute(gemm_mma<1>, cudaFuncAttributeMaxDynamicSharedMemorySize, GEMM_SMEM);

    dim3 ggrid(NBLK, 2, N_);

    // 0) operand conversion (x + 3 weights in one launch)
    cvt_all_k<<<XBLK + 3 * WBLK_PER, 256>>>(x, w_pre, w_gate, w_pw, xh, wh);

    // 1) h0 = conv1x1(x, w_pre) [fp16] + GN1 partials
    gemm_mma<0><<<ggrid, 256, GEMM_SMEM>>>(wh, xh, h0, part1, nullptr, nullptr);
    // 2) h = silu(gn(h0)) -> fp16 + fused -> fp16
    gn_silu_rowcol_k<<<N_ * C_, 256>>>(h0, part1, g1, b1, hh, fu);
    // 3) gated = fused * sigmoid(conv1x1(h,w_gate)+b) -> fp16
    gemm_mma<1><<<ggrid, 256, GEMM_SMEM>>>(wh + C_*C_, hh, gt, nullptr, fu, b_gate);
    // 4) depthwise 3x3 fp16 -> fp16
    dw3x3_k<<<N_ * C_, 256>>>(gt, w_dw, dh);
    // 5) y = conv1x1(dw, w_pw) [fp16] + GN2 partials
    gemm_mma<0><<<ggrid, 256, GEMM_SMEM>>>(wh + 2*C_*C_, dh, y16, part2, nullptr, nullptr);
    // 6) out = silu(gn(y)) -> fp32
    gn_silu_out_k<<<N_ * C_, 256>>>(y16, part2, g2, b2, out);
}